// round 17
// baseline (speedup 1.0000x reference)
#include <cuda_runtime.h>
#include <cuda_bf16.h>
#include <cstdint>
#include <cstddef>

// ---------------------------------------------------------------------------
// SAGE 3-layer GraphSAGE. R17 = R16 +
//   (1) layer-0 agg kept fp32 (400B/row vs 512B padded split); gemm0 splits
//       BOTH A phases in-kernel (x self + a0 neigh), -58MB DRAM.
//   (2) dual-dst gather0: 2 rows/warp, interleaved batches -> 2x MLP.
// ---------------------------------------------------------------------------

namespace {
constexpr int kN1 = 262144, kN2 = 32768, kN3 = 8192;
constexpr int kE0 = 1310720, kE1 = 327680, kE2 = 81920;
constexpr int kF = 100, kH = 256, kC = 47;
constexpr int kNT = kN1 + kN2 + kN3;
constexpr int kET = kE0 + kE1 + kE2;
constexpr int kHalf = kN1 / 2;
}  // namespace

__device__ float g_h1[(size_t)kN1 * kH];
__device__ float g_h2[(size_t)kN2 * kH];
__device__ float g_a0f[(size_t)kN1 * kF];   // fp32 layer-0 neigh mean

__device__ int g_ints[2 * kNT + 3];
__device__ int g_off[kNT];
__device__ int g_csc[kET];

__device__ __nv_bfloat16 g_h1s_hi[(size_t)kN2 * 256], g_h1s_lo[(size_t)kN2 * 256];
__device__ __nv_bfloat16 g_a1_hi[(size_t)kN2 * 256], g_a1_lo[(size_t)kN2 * 256];
__device__ __nv_bfloat16 g_h2s_hi[(size_t)kN3 * 256], g_h2s_lo[(size_t)kN3 * 256];
__device__ __nv_bfloat16 g_a2_hi[(size_t)kN3 * 256], g_a2_lo[(size_t)kN3 * 256];

__device__ __nv_bfloat16 g_w0_hi[2 * 128 * 256], g_w0_lo[2 * 128 * 256];
__device__ __nv_bfloat16 g_w1_hi[2 * 256 * 256], g_w1_lo[2 * 256 * 256];
__device__ __nv_bfloat16 g_w2_hi[2 * 256 * 128], g_w2_lo[2 * 256 * 128];

// ======================== PTX helpers =========================================
__device__ __forceinline__ uint32_t smem_u32(const void* p) {
    return (uint32_t)__cvta_generic_to_shared(p);
}
__device__ __forceinline__ void ldsm4(uint32_t* r, uint32_t addr) {
    asm volatile("ldmatrix.sync.aligned.m8n8.x4.shared.b16 {%0,%1,%2,%3}, [%4];"
                 : "=r"(r[0]), "=r"(r[1]), "=r"(r[2]), "=r"(r[3]) : "r"(addr));
}
__device__ __forceinline__ void ldsm4t(uint32_t* r, uint32_t addr) {
    asm volatile("ldmatrix.sync.aligned.m8n8.x4.trans.shared.b16 {%0,%1,%2,%3}, [%4];"
                 : "=r"(r[0]), "=r"(r[1]), "=r"(r[2]), "=r"(r[3]) : "r"(addr));
}
__device__ __forceinline__ void mma_bf16(float* d, const uint32_t* a,
                                         uint32_t b0, uint32_t b1) {
    asm volatile(
        "mma.sync.aligned.m16n8k16.row.col.f32.bf16.bf16.f32 "
        "{%0,%1,%2,%3}, {%4,%5,%6,%7}, {%8,%9}, {%0,%1,%2,%3};"
        : "+f"(d[0]), "+f"(d[1]), "+f"(d[2]), "+f"(d[3])
        : "r"(a[0]), "r"(a[1]), "r"(a[2]), "r"(a[3]), "r"(b0), "r"(b1));
}
__device__ __forceinline__ uint32_t cvt_bf16x2(float a, float b) {
    uint32_t r;
    asm("cvt.rn.bf16x2.f32 %0, %1, %2;" : "=r"(r) : "f"(b), "f"(a));
    return r;
}
__device__ __forceinline__ void cp_async16(uint32_t saddr, const void* gptr) {
    asm volatile("cp.async.ca.shared.global [%0], [%1], 16;"
                 :: "r"(saddr), "l"(gptr));
}
#define CP_COMMIT() asm volatile("cp.async.commit_group;" ::: "memory")

// ======================== fused CSC build =====================================
__global__ void zero_int(int* __restrict__ p, int n) {
    int i = blockIdx.x * blockDim.x + threadIdx.x;
    if (i < n) p[i] = 0;
}
__global__ void count3(const int* __restrict__ ed0, const int* __restrict__ ed1,
                       const int* __restrict__ ed2, int* __restrict__ cnt) {
    int i = blockIdx.x * blockDim.x + threadIdx.x;
    if (i < kE0) {
        atomicAdd(cnt + __ldg(ed0 + i), 1);
    } else if (i < kE0 + kE1) {
        atomicAdd(cnt + kN1 + __ldg(ed1 + (i - kE0)), 1);
    } else if (i < kET) {
        atomicAdd(cnt + kN1 + kN2 + __ldg(ed2 + (i - kE0 - kE1)), 1);
    }
}
__global__ void reserve3(const int* __restrict__ cnt, int* __restrict__ off,
                         int* __restrict__ cursor) {
    __shared__ int s[256];
    __shared__ int base;
    int b = blockIdx.x, tid = threadIdx.x;
    int seg;
    if (b < kN1 / 256)               seg = 0;
    else if (b < (kN1 + kN2) / 256)  seg = 1;
    else                             seg = 2;
    int i = b * 256 + tid;
    int v = __ldg(cnt + i);
    s[tid] = v;
    __syncthreads();
#pragma unroll
    for (int dd = 1; dd < 256; dd <<= 1) {
        int t = (tid >= dd) ? s[tid - dd] : 0;
        __syncthreads();
        s[tid] += t;
        __syncthreads();
    }
    if (tid == 255) base = atomicAdd(cursor + seg, s[255]);
    __syncthreads();
    off[i] = base + s[tid] - v;
}
__global__ void fill3(const int* __restrict__ es0, const int* __restrict__ ed0,
                      const int* __restrict__ es1, const int* __restrict__ ed1,
                      const int* __restrict__ es2, const int* __restrict__ ed2,
                      const int* __restrict__ off, int* __restrict__ cur,
                      int* __restrict__ csc) {
    int i = blockIdx.x * blockDim.x + threadIdx.x;
    if (i < kE0) {
        int d = __ldg(ed0 + i);
        int p = atomicAdd(cur + d, 1);
        csc[__ldg(off + d) + p] = __ldg(es0 + i);
    } else if (i < kE0 + kE1) {
        int j = i - kE0;
        int d = kN1 + __ldg(ed1 + j);
        int p = atomicAdd(cur + d, 1);
        csc[kE0 + __ldg(off + d) + p] = __ldg(es1 + j);
    } else if (i < kET) {
        int j = i - kE0 - kE1;
        int d = kN1 + kN2 + __ldg(ed2 + j);
        int p = atomicAdd(cur + d, 1);
        csc[kE0 + kE1 + __ldg(off + d) + p] = __ldg(es2 + j);
    }
}

// ======================== gather0: dual-dst, fp32 output ======================
// Each warp handles 2 consecutive dsts with interleaved 4-edge batches
// (up to 8 independent row loads in flight). Writes fp32 mean rows.
template <int K>
__global__ void __launch_bounds__(128, 12)
gather0_kern(const float* __restrict__ feat, const int* __restrict__ off,
             const int* __restrict__ cnt, const int* __restrict__ csc,
             int dBase, int nd, float* __restrict__ aggf) {
    constexpr int NV = K / 4;      // 25
    static_assert(NV <= 32, "single float4 column per lane");
    int w = (blockIdx.x * blockDim.x + threadIdx.x) >> 5;
    int lane = threadIdx.x & 31;
    int d0 = dBase + 2 * w;
    if (d0 >= dBase + nd) return;
    int d1 = d0 + 1;               // nd even for all call sites
    int oA = __ldg(off + d0), degA = __ldg(cnt + d0);
    int oB = __ldg(off + d1), degB = __ldg(cnt + d1);
    const bool act = lane < NV;
    float4 accA = make_float4(0.f, 0.f, 0.f, 0.f);
    float4 accB = make_float4(0.f, 0.f, 0.f, 0.f);
    int degM = degA > degB ? degA : degB;
    for (int e = 0; e < degM; e += 4) {
        int ia[4], ib[4];
#pragma unroll
        for (int u = 0; u < 4; ++u) {
            ia[u] = (e + u < degA) ? __ldg(csc + oA + e + u) : -1;
            ib[u] = (e + u < degB) ? __ldg(csc + oB + e + u) : -1;
        }
        if (act) {
#pragma unroll
            for (int u = 0; u < 4; ++u) {
                if (ia[u] >= 0) {
                    float4 f = __ldg(reinterpret_cast<const float4*>(
                                         feat + (size_t)ia[u] * K) + lane);
                    accA.x += f.x; accA.y += f.y; accA.z += f.z; accA.w += f.w;
                }
            }
#pragma unroll
            for (int u = 0; u < 4; ++u) {
                if (ib[u] >= 0) {
                    float4 f = __ldg(reinterpret_cast<const float4*>(
                                         feat + (size_t)ib[u] * K) + lane);
                    accB.x += f.x; accB.y += f.y; accB.z += f.z; accB.w += f.w;
                }
            }
        }
    }
    if (!act) return;
    float rA = 1.f / fmaxf((float)degA, 1.f);
    float rB = 1.f / fmaxf((float)degB, 1.f);
    float4 wA = make_float4(accA.x * rA, accA.y * rA, accA.z * rA, accA.w * rA);
    float4 wB = make_float4(accB.x * rB, accB.y * rB, accB.z * rB, accB.w * rB);
    *(reinterpret_cast<float4*>(aggf + (size_t)d0 * K) + lane) = wA;
    *(reinterpret_cast<float4*>(aggf + (size_t)d1 * K) + lane) = wB;
}

// ======================== gather-mean + split (layers 1/2) ====================
template <int K, int KPAD>
__global__ void gather_split(const float* __restrict__ feat,
                             const int* __restrict__ off,
                             const int* __restrict__ cnt,
                             const int* __restrict__ csc, int ndst,
                             uint2* __restrict__ hi, uint2* __restrict__ lo) {
    constexpr int NV = K / 4;
    constexpr int PV = KPAD / 4;
    constexpr int PER = (PV + 31) / 32;
    int d = (blockIdx.x * blockDim.x + threadIdx.x) >> 5;
    int lane = threadIdx.x & 31;
    if (d >= ndst) return;
    int o0 = __ldg(off + d);
    int deg = __ldg(cnt + d);
    float4 acc[PER];
#pragma unroll
    for (int p = 0; p < PER; ++p) acc[p] = make_float4(0.f, 0.f, 0.f, 0.f);
    int e = 0;
    for (; e + 8 <= deg; e += 8) {
        const float4* rr[8];
#pragma unroll
        for (int u = 0; u < 8; ++u) {
            int s = __ldg(csc + o0 + e + u);
            rr[u] = reinterpret_cast<const float4*>(feat + (size_t)s * K);
        }
#pragma unroll
        for (int p = 0; p < PER; ++p) {
            int v = lane + 32 * p;
            if (v < NV) {
                float4 f[8];
#pragma unroll
                for (int u = 0; u < 8; ++u) f[u] = __ldg(rr[u] + v);
#pragma unroll
                for (int u = 0; u < 8; ++u) {
                    acc[p].x += f[u].x; acc[p].y += f[u].y;
                    acc[p].z += f[u].z; acc[p].w += f[u].w;
                }
            }
        }
    }
    for (; e + 4 <= deg; e += 4) {
        const float4* rr[4];
#pragma unroll
        for (int u = 0; u < 4; ++u) {
            int s = __ldg(csc + o0 + e + u);
            rr[u] = reinterpret_cast<const float4*>(feat + (size_t)s * K);
        }
#pragma unroll
        for (int p = 0; p < PER; ++p) {
            int v = lane + 32 * p;
            if (v < NV) {
                float4 f[4];
#pragma unroll
                for (int u = 0; u < 4; ++u) f[u] = __ldg(rr[u] + v);
#pragma unroll
                for (int u = 0; u < 4; ++u) {
                    acc[p].x += f[u].x; acc[p].y += f[u].y;
                    acc[p].z += f[u].z; acc[p].w += f[u].w;
                }
            }
        }
    }
    for (; e < deg; ++e) {
        int s = __ldg(csc + o0 + e);
        const float4* row = reinterpret_cast<const float4*>(feat + (size_t)s * K);
#pragma unroll
        for (int p = 0; p < PER; ++p) {
            int v = lane + 32 * p;
            if (v < NV) {
                float4 f = __ldg(row + v);
                acc[p].x += f.x; acc[p].y += f.y; acc[p].z += f.z; acc[p].w += f.w;
            }
        }
    }
    float r = 1.f / fmaxf((float)deg, 1.f);
#pragma unroll
    for (int p = 0; p < PER; ++p) {
        int v = lane + 32 * p;
        if (v >= NV) continue;
        float4 w;
        w.x = acc[p].x * r; w.y = acc[p].y * r;
        w.z = acc[p].z * r; w.w = acc[p].w * r;
        uint32_t hx = __float_as_uint(w.x) & 0xFFFF0000u;
        uint32_t hy = __float_as_uint(w.y) & 0xFFFF0000u;
        uint32_t hz = __float_as_uint(w.z) & 0xFFFF0000u;
        uint32_t hw = __float_as_uint(w.w) & 0xFFFF0000u;
        uint2 ho, lv;
        ho.x = (hx >> 16) | hy;
        ho.y = (hz >> 16) | hw;
        lv.x = cvt_bf16x2(w.x - __uint_as_float(hx), w.y - __uint_as_float(hy));
        lv.y = cvt_bf16x2(w.z - __uint_as_float(hz), w.w - __uint_as_float(hw));
        size_t oidx = (size_t)d * PV + v;
        hi[oidx] = ho;
        lo[oidx] = lv;
    }
}

// ======================== misc small kernels ==================================
template <int K1, int NCOLS, int KPAD, int NPAD>
__global__ void prep_w(const float* __restrict__ Ws, const float* __restrict__ Wn,
                       __nv_bfloat16* __restrict__ hi, __nv_bfloat16* __restrict__ lo) {
    int idx = blockIdx.x * blockDim.x + threadIdx.x;
    constexpr int TOT = 2 * KPAD * NPAD;
    if (idx >= TOT) return;
    int phase = idx / (KPAD * NPAD);
    int rem = idx % (KPAD * NPAD);
    int k = rem / NPAD, n = rem % NPAD;
    float v = 0.f;
    if (k < K1 && n < NCOLS) v = (phase ? Wn : Ws)[(size_t)k * NCOLS + n];
    uint32_t h = __float_as_uint(v) & 0xFFFF0000u;
    hi[idx] = __ushort_as_bfloat16((unsigned short)(h >> 16));
    lo[idx] = __float2bfloat16(v - __uint_as_float(h));
}

// ======================== 2-stage cp.async bf16x3 GEMM ========================
// F32A: both A phases load fp32 (self = Asf, neigh = Anf; ld = KF) and split
// to bf16 in-kernel. Otherwise A phases use cp.async from pre-split buffers.
template <int KPAD, int KF, int NCOLS, int NPAD, bool RELU, bool WSPLIT, bool F32A>
__global__ void __launch_bounds__(256, 2)
gemm_mma(const float* __restrict__ Asf, const float* __restrict__ Anf,
         const __nv_bfloat16* __restrict__ As_hi, const __nv_bfloat16* __restrict__ As_lo,
         const __nv_bfloat16* __restrict__ An_hi, const __nv_bfloat16* __restrict__ An_lo,
         const __nv_bfloat16* __restrict__ W_hi, const __nv_bfloat16* __restrict__ W_lo,
         const float* __restrict__ bias, float* __restrict__ out,
         uint32_t* __restrict__ sp_hi, uint32_t* __restrict__ sp_lo,
         int split_rows, int mBase) {
    constexpr int BM = 128;
    constexpr int BK = 32;
    constexpr int AST = 40;
    constexpr int BST = 136;
    constexpr int ABYTES = BM * AST * 2;
    constexpr int BBYTES = BK * BST * 2;
    constexpr int SSTRIDE = 2 * ABYTES + 2 * BBYTES;
    constexpr int CPP = KPAD / BK;
    constexpr int NCH = 2 * CPP;

    extern __shared__ char smem[];
    const uint32_t su = smem_u32(smem);

    const int tid = threadIdx.x;
    const int lane = tid & 31, wid = tid >> 5;
    const int wm = wid & 1, wn = wid >> 1;
    const int nBlock = blockIdx.x * 128, mBlock = mBase + blockIdx.y * BM;

    const int ar = tid >> 1;
    const int ab = (tid & 1) * 32;
    const int br = tid >> 4;
    const int bc = tid & 15;

    auto issue_chunk = [&](int c) {
        const int stage = c & 1;
        const int phase = c / CPP;
        const int k0 = (c % CPP) * BK;
        if (F32A) {
            const float* Af = phase ? Anf : Asf;
            const int c0 = (tid & 1) * 16;
            const int gm = mBlock + ar;
            uint32_t hv[8], lv[8];
#pragma unroll
            for (int j = 0; j < 4; ++j) {
                int col = k0 + c0 + 4 * j;
                float4 v = make_float4(0.f, 0.f, 0.f, 0.f);
                if (col < KF)
                    v = *reinterpret_cast<const float4*>(Af + (size_t)gm * KF + col);
                uint32_t hx = __float_as_uint(v.x) & 0xFFFF0000u;
                uint32_t hy = __float_as_uint(v.y) & 0xFFFF0000u;
                uint32_t hz = __float_as_uint(v.z) & 0xFFFF0000u;
                uint32_t h3 = __float_as_uint(v.w) & 0xFFFF0000u;
                hv[2 * j]     = (hx >> 16) | hy;
                hv[2 * j + 1] = (hz >> 16) | h3;
                lv[2 * j]     = cvt_bf16x2(v.x - __uint_as_float(hx),
                                           v.y - __uint_as_float(hy));
                lv[2 * j + 1] = cvt_bf16x2(v.z - __uint_as_float(hz),
                                           v.w - __uint_as_float(h3));
            }
            char* dst = smem + stage * SSTRIDE + 2 * (ar * AST + c0);
            *reinterpret_cast<uint4*>(dst)      = make_uint4(hv[0], hv[1], hv[2], hv[3]);
            *reinterpret_cast<uint4*>(dst + 16) = make_uint4(hv[4], hv[5], hv[6], hv[7]);
            char* dstl = dst + ABYTES;
            *reinterpret_cast<uint4*>(dstl)      = make_uint4(lv[0], lv[1], lv[2], lv[3]);
            *reinterpret_cast<uint4*>(dstl + 16) = make_uint4(lv[4], lv[5], lv[6], lv[7]);
        } else {
            const __nv_bfloat16* Ahi = phase ? An_hi : As_hi;
            const __nv_bfloat16* Alo = phase ? An_lo : As_lo;
            const uint32_t sb = su + stage * SSTRIDE;
            size_t g = (size_t)(mBlock + ar) * KPAD + k0 + ab / 2;
            uint32_t sa = sb + 2u * (uint32_t)(ar * AST) + (uint32_t)ab;
            cp_async16(sa, Ahi + g);
            cp_async16(sa + 16, Ahi + g + 8);
            cp_async16(sa + (uint32_t)ABYTES, Alo + g);
            cp_async16(sa + (uint32_t)ABYTES + 16, Alo + g + 8);
        }
        {
            const uint32_t sb = su + stage * SSTRIDE;
            const __nv_bfloat16* wb =
                W_hi + (size_t)phase * KPAD * NPAD + (size_t)k0 * NPAD + nBlock;
            const __nv_bfloat16* wl =
                W_lo + (size_t)phase * KPAD * NPAD + (size_t)k0 * NPAD + nBlock;
#pragma unroll
            for (int it = 0; it < 2; ++it) {
                int r = br + it * 16;
                size_t g = (size_t)r * NPAD + bc * 8;
                uint32_t sbb = sb + 2u * (uint32_t)ABYTES +
                               2u * (uint32_t)(r * BST + bc * 8);
                cp_async16(sbb, wb + g);
                cp_async16(sbb + (uint32_t)BBYTES, wl + g);
            }
        }
        CP_COMMIT();
    };

    float acc[4][4][4];
#pragma unroll
    for (int i = 0; i < 4; i++)
#pragma unroll
        for (int j = 0; j < 4; j++)
#pragma unroll
            for (int r = 0; r < 4; r++) acc[i][j][r] = 0.f;

    const int lr = lane & 15;
    const int lc = (lane >> 4) * 8;
    const uint32_t aOff = 2u * (uint32_t)((wm * 64 + lr) * AST + lc);
    const uint32_t bOff = 2u * (uint32_t)ABYTES + 2u * (uint32_t)(lr * BST + wn * 32 + lc);

    issue_chunk(0);
    for (int c = 0; c < NCH; ++c) {
        if (c + 1 < NCH) {
            issue_chunk(c + 1);
            asm volatile("cp.async.wait_group 1;" ::: "memory");
        } else {
            asm volatile("cp.async.wait_group 0;" ::: "memory");
        }
        __syncthreads();
        const uint32_t sb = su + (c & 1) * SSTRIDE;
        const uint32_t aHiBase = sb + aOff;
        const uint32_t bHiBase = sb + bOff;
#pragma unroll
        for (int k16 = 0; k16 < BK / 16; ++k16) {
            const uint32_t kk = k16 * 16;
            uint32_t ah[4][4], bh[2][4];
#pragma unroll
            for (int p = 0; p < 2; ++p)
                ldsm4t(bh[p], bHiBase + 2u * (kk * BST + p * 16));
#pragma unroll
            for (int mt = 0; mt < 4; ++mt)
                ldsm4(ah[mt], aHiBase + 2u * (mt * 16 * AST + kk));
#pragma unroll
            for (int mt = 0; mt < 4; ++mt)
#pragma unroll
                for (int nt = 0; nt < 4; ++nt)
                    mma_bf16(acc[mt][nt], ah[mt], bh[nt >> 1][(nt & 1) * 2],
                             bh[nt >> 1][(nt & 1) * 2 + 1]);
            {
                uint32_t bl[2][4];
#pragma unroll
                for (int p = 0; p < 2; ++p)
                    ldsm4t(bl[p], bHiBase + (uint32_t)BBYTES + 2u * (kk * BST + p * 16));
#pragma unroll
                for (int mt = 0; mt < 4; ++mt)
#pragma unroll
                    for (int nt = 0; nt < 4; ++nt)
                        mma_bf16(acc[mt][nt], ah[mt], bl[nt >> 1][(nt & 1) * 2],
                                 bl[nt >> 1][(nt & 1) * 2 + 1]);
            }
            {
                uint32_t al[4][4];
#pragma unroll
                for (int mt = 0; mt < 4; ++mt)
                    ldsm4(al[mt], aHiBase + (uint32_t)ABYTES + 2u * (mt * 16 * AST + kk));
#pragma unroll
                for (int mt = 0; mt < 4; ++mt)
#pragma unroll
                    for (int nt = 0; nt < 4; ++nt)
                        mma_bf16(acc[mt][nt], al[mt], bh[nt >> 1][(nt & 1) * 2],
                                 bh[nt >> 1][(nt & 1) * 2 + 1]);
            }
        }
        __syncthreads();
    }

#pragma unroll
    for (int mt = 0; mt < 4; ++mt) {
        const int gmA = mBlock + wm * 64 + mt * 16 + (lane >> 2);
#pragma unroll
        for (int half = 0; half < 2; ++half) {
            const int gm = gmA + half * 8;
            float* orow = out + (size_t)gm * NCOLS;
#pragma unroll
            for (int nt = 0; nt < 4; ++nt) {
                const int gn = nBlock + wn * 32 + nt * 8 + (lane & 3) * 2;
                float v0 = acc[mt][nt][half * 2 + 0];
                float v1 = acc[mt][nt][half * 2 + 1];
                if constexpr (NCOLS % 128 == 0) {
                    v0 += __ldg(bias + gn);
                    v1 += __ldg(bias + gn + 1);
                    if (RELU) { v0 = fmaxf(v0, 0.f); v1 = fmaxf(v1, 0.f); }
                    *reinterpret_cast<float2*>(orow + gn) = make_float2(v0, v1);
                    if (WSPLIT && gm < split_rows) {
                        uint32_t h0 = __float_as_uint(v0) & 0xFFFF0000u;
                        uint32_t h1 = __float_as_uint(v1) & 0xFFFF0000u;
                        size_t so = (size_t)gm * (NCOLS / 2) + (gn >> 1);
                        sp_hi[so] = (h0 >> 16) | h1;
                        sp_lo[so] = cvt_bf16x2(v0 - __uint_as_float(h0),
                                               v1 - __uint_as_float(h1));
                    }
                } else {
                    if (gn < NCOLS) {
                        float v = v0 + __ldg(bias + gn);
                        if (RELU) v = fmaxf(v, 0.f);
                        orow[gn] = v;
                    }
                    if (gn + 1 < NCOLS) {
                        float v = v1 + __ldg(bias + gn + 1);
                        if (RELU) v = fmaxf(v, 0.f);
                        orow[gn + 1] = v;
                    }
                }
            }
        }
    }
}

// ======================== host launcher ======================================
static inline int cdiv_host(long long a, long long b) { return (int)((a + b - 1) / b); }

extern "C" void kernel_launch(void* const* d_in, const int* in_sizes, int n_in,
                              void* d_out, int out_size) {
    (void)in_sizes; (void)n_in; (void)out_size;
    const float* x   = (const float*)d_in[0];
    const int* es0   = (const int*)d_in[1];
    const int* ed0   = (const int*)d_in[2];
    const int* es1   = (const int*)d_in[3];
    const int* ed1   = (const int*)d_in[4];
    const int* es2   = (const int*)d_in[5];
    const int* ed2   = (const int*)d_in[6];
    const float* Ws0 = (const float*)d_in[7];
    const float* Wn0 = (const float*)d_in[8];
    const float* b0  = (const float*)d_in[9];
    const float* Ws1 = (const float*)d_in[10];
    const float* Wn1 = (const float*)d_in[11];
    const float* b1  = (const float*)d_in[12];
    const float* Ws2 = (const float*)d_in[13];
    const float* Wn2 = (const float*)d_in[14];
    const float* b2  = (const float*)d_in[15];
    float* out = (float*)d_out;

    float *h1, *h2, *a0f;
    cudaGetSymbolAddress((void**)&h1, g_h1);
    cudaGetSymbolAddress((void**)&h2, g_h2);
    cudaGetSymbolAddress((void**)&a0f, g_a0f);
    int *ints, *off, *csc;
    cudaGetSymbolAddress((void**)&ints, g_ints);
    cudaGetSymbolAddress((void**)&off, g_off);
    cudaGetSymbolAddress((void**)&csc, g_csc);
    int* cnt = ints;
    int* cur = ints + kNT;
    int* cursor = ints + 2 * kNT;

    __nv_bfloat16 *h1s_hi, *h1s_lo, *a1_hi, *a1_lo, *h2s_hi, *h2s_lo, *a2_hi, *a2_lo;
    cudaGetSymbolAddress((void**)&h1s_hi, g_h1s_hi);
    cudaGetSymbolAddress((void**)&h1s_lo, g_h1s_lo);
    cudaGetSymbolAddress((void**)&a1_hi, g_a1_hi);
    cudaGetSymbolAddress((void**)&a1_lo, g_a1_lo);
    cudaGetSymbolAddress((void**)&h2s_hi, g_h2s_hi);
    cudaGetSymbolAddress((void**)&h2s_lo, g_h2s_lo);
    cudaGetSymbolAddress((void**)&a2_hi, g_a2_hi);
    cudaGetSymbolAddress((void**)&a2_lo, g_a2_lo);
    __nv_bfloat16 *w0h, *w0l, *w1h, *w1l, *w2h, *w2l;
    cudaGetSymbolAddress((void**)&w0h, g_w0_hi);
    cudaGetSymbolAddress((void**)&w0l, g_w0_lo);
    cudaGetSymbolAddress((void**)&w1h, g_w1_hi);
    cudaGetSymbolAddress((void**)&w1l, g_w1_lo);
    cudaGetSymbolAddress((void**)&w2h, g_w2_hi);
    cudaGetSymbolAddress((void**)&w2l, g_w2_lo);

    const int T = 256;
    constexpr int SMEM_SZ = 2 * (2 * 128 * 40 * 2 + 2 * 32 * 136 * 2);  // 75776

    cudaFuncSetAttribute(gemm_mma<128, 100, 256, 256, true, true, true>,
                         cudaFuncAttributeMaxDynamicSharedMemorySize, SMEM_SZ);
    cudaFuncSetAttribute(gemm_mma<256, 256, 256, 256, true, true, false>,
                         cudaFuncAttributeMaxDynamicSharedMemorySize, SMEM_SZ);
    cudaFuncSetAttribute(gemm_mma<256, 256, 47, 128, false, false, false>,
                         cudaFuncAttributeMaxDynamicSharedMemorySize, SMEM_SZ);

    static cudaStream_t side = nullptr;
    static cudaEvent_t evFork = nullptr, evPrep = nullptr, evGA = nullptr,
                       evG0A = nullptr;
    if (!side) {
        cudaStreamCreateWithFlags(&side, cudaStreamNonBlocking);
        cudaEventCreateWithFlags(&evFork, cudaEventDisableTiming);
        cudaEventCreateWithFlags(&evPrep, cudaEventDisableTiming);
        cudaEventCreateWithFlags(&evGA, cudaEventDisableTiming);
        cudaEventCreateWithFlags(&evG0A, cudaEventDisableTiming);
    }

    // ---- fork: side stream does weight prep
    cudaEventRecord(evFork, 0);
    cudaStreamWaitEvent(side, evFork, 0);
    prep_w<100, 256, 128, 256><<<cdiv_host(2 * 128 * 256, T), T, 0, side>>>(
        Ws0, Wn0, w0h, w0l);
    prep_w<256, 256, 256, 256><<<cdiv_host(2 * 256 * 256, T), T, 0, side>>>(
        Ws1, Wn1, w1h, w1l);
    prep_w<256, 47, 256, 128><<<cdiv_host(2 * 256 * 128, T), T, 0, side>>>(
        Ws2, Wn2, w2h, w2l);
    cudaEventRecord(evPrep, side);

    // ---- main: fused CSC build
    zero_int<<<cdiv_host(2 * kNT + 3, T), T>>>(ints, 2 * kNT + 3);
    count3<<<cdiv_host(kET, T), T>>>(ed0, ed1, ed2, cnt);
    reserve3<<<kNT / 256, 256>>>(cnt, off, cursor);
    fill3<<<cdiv_host(kET, T), T>>>(es0, ed0, es1, ed1, es2, ed2, off, cur, csc);

    // ---- gather0 halves (dual-dst: 8 dsts per 128-thr block)
    gather0_kern<100><<<kHalf / 8, 128>>>(x, off, cnt, csc, 0, kHalf, a0f);
    cudaEventRecord(evGA, 0);
    gather0_kern<100><<<kHalf / 8, 128>>>(x, off, cnt, csc, kHalf, kHalf, a0f);

    // side: gemm0-A on rows [0, kHalf) — concurrent with gather0 half B
    cudaStreamWaitEvent(side, evGA, 0);
    gemm_mma<128, 100, 256, 256, true, true, true><<<dim3(2, kHalf / 128), T, SMEM_SZ, side>>>(
        x, a0f, nullptr, nullptr, nullptr, nullptr, w0h, w0l, b0, h1,
        (uint32_t*)h1s_hi, (uint32_t*)h1s_lo, kN2, 0);
    cudaEventRecord(evG0A, side);

    // main: gemm0-B on rows [kHalf, kN1)
    cudaStreamWaitEvent(0, evPrep, 0);
    gemm_mma<128, 100, 256, 256, true, true, true><<<dim3(2, kHalf / 128), T, SMEM_SZ>>>(
        x, a0f, nullptr, nullptr, nullptr, nullptr, w0h, w0l, b0, h1,
        (uint32_t*)h1s_hi, (uint32_t*)h1s_lo, kN2, kHalf);

    cudaStreamWaitEvent(0, evG0A, 0);

    // ---------------- layer 1
    gather_split<256, 256><<<kN2 / 8, T>>>(h1, off + kN1, cnt + kN1, csc + kE0,
                                           kN2, (uint2*)a1_hi, (uint2*)a1_lo);
    gemm_mma<256, 256, 256, 256, true, true, false><<<dim3(2, kN2 / 128), T, SMEM_SZ>>>(
        nullptr, nullptr, h1s_hi, h1s_lo, a1_hi, a1_lo, w1h, w1l, b1, h2,
        (uint32_t*)h2s_hi, (uint32_t*)h2s_lo, kN3, 0);

    // ---------------- layer 2
    gather_split<256, 256><<<kN3 / 8, T>>>(h2, off + kN1 + kN2, cnt + kN1 + kN2,
                                           csc + kE0 + kE1, kN3,
                                           (uint2*)a2_hi, (uint2*)a2_lo);
    gemm_mma<256, 256, 47, 128, false, false, false><<<dim3(1, kN3 / 128), T, SMEM_SZ>>>(
        nullptr, nullptr, h2s_hi, h2s_lo, a2_hi, a2_lo, w2h, w2l, b2, out,
        nullptr, nullptr, 0, 0);
}